// round 15
// baseline (speedup 1.0000x reference)
#include <cuda_runtime.h>
#include <cuda_bf16.h>
#include <stdint.h>

#define BB 2
#define SEQ 2048
#define DMODEL 1024
#define NH 16
#define DH 64
#define MROWS (BB * SEQ)     // 4096
#define KE (3 * DMODEL)      // 3072

// Scratch (allocation-free)
__device__ float g_q[MROWS * DMODEL];
__device__ float g_k[MROWS * DMODEL];
__device__ float g_v[MROWS * DMODEL];
__device__ float g_ao[MROWS * DMODEL];
__device__ __nv_bfloat16 g_xe[3][(size_t)MROWS * KE];   // 3 x 24 MB
__device__ __nv_bfloat16 g_we[4][(size_t)DMODEL * KE];  // 4 x 6 MB

// packed KV tile geometry: tile = 128 keys x 64 cols bf16 (128B rows, SW128)
#define KVTILE_B 16384
#define KV_LO_ELEMS 4194304   // 512 tiles * 8192 elems (hi buf); lo at +this

// ---------------------------------------------------------------------------
// helpers
// ---------------------------------------------------------------------------
__device__ __forceinline__ uint32_t pk2(float lo, float hi) {
    uint32_t r;
    asm("cvt.rn.bf16x2.f32 %0, %1, %2;" : "=r"(r) : "f"(hi), "f"(lo));
    return r;
}
__device__ __forceinline__ float lof(uint32_t u) { return __uint_as_float(u << 16); }
__device__ __forceinline__ float hif(uint32_t u) { return __uint_as_float(u & 0xffff0000u); }

__device__ __forceinline__ void ldsm4(uint32_t& r0, uint32_t& r1,
                                      uint32_t& r2, uint32_t& r3, uint32_t addr) {
    asm volatile("ldmatrix.sync.aligned.m8n8.x4.shared.b16 {%0,%1,%2,%3}, [%4];"
                 : "=r"(r0), "=r"(r1), "=r"(r2), "=r"(r3) : "r"(addr));
}
__device__ __forceinline__ void ldsm4t(uint32_t& r0, uint32_t& r1,
                                       uint32_t& r2, uint32_t& r3, uint32_t addr) {
    asm volatile("ldmatrix.sync.aligned.m8n8.x4.trans.shared.b16 {%0,%1,%2,%3}, [%4];"
                 : "=r"(r0), "=r"(r1), "=r"(r2), "=r"(r3) : "r"(addr));
}
__device__ __forceinline__ void mma16816(float* d, const uint32_t* a,
                                         uint32_t b0, uint32_t b1) {
    asm volatile(
        "mma.sync.aligned.m16n8k16.row.col.f32.bf16.bf16.f32 "
        "{%0,%1,%2,%3}, {%4,%5,%6,%7}, {%8,%9}, {%0,%1,%2,%3};"
        : "+f"(d[0]), "+f"(d[1]), "+f"(d[2]), "+f"(d[3])
        : "r"(a[0]), "r"(a[1]), "r"(a[2]), "r"(a[3]), "r"(b0), "r"(b1));
}
__device__ __forceinline__ uint32_t sw128b(uint32_t b) {
    return b ^ ((b >> 3) & 0x70);
}
__device__ __forceinline__ uint32_t sw64(uint32_t b) {
    return b ^ ((b >> 3) & 0x30);
}
__device__ __forceinline__ void cpasync16(uint32_t dst, const void* src) {
    asm volatile("cp.async.cg.shared.global [%0], [%1], 16;" :: "r"(dst), "l"(src));
}
__device__ __forceinline__ void cp_commit() {
    asm volatile("cp.async.commit_group;");
}
__device__ __forceinline__ void cp_wait1() {
    asm volatile("cp.async.wait_group 1;");
}
__device__ __forceinline__ void cp_wait0() {
    asm volatile("cp.async.wait_group 0;");
}

// ---------------------------------------------------------------------------
// Expansion: act -> [hi|lo|hi], weights -> [hi|hi|lo]  (proven math)
// ---------------------------------------------------------------------------
__device__ __forceinline__ void expand_row(const float* __restrict__ X,
                                           __nv_bfloat16* __restrict__ E, bool isw)
{
    int idx = blockIdx.x * 256 + threadIdx.x;
    int m = idx >> 8;
    int c = (idx & 255) * 4;
    float4 x = *(const float4*)(X + (size_t)m * DMODEL + c);

    __nv_bfloat16 h[4], l[4];
    h[0] = __float2bfloat16(x.x); l[0] = __float2bfloat16(x.x - __bfloat162float(h[0]));
    h[1] = __float2bfloat16(x.y); l[1] = __float2bfloat16(x.y - __bfloat162float(h[1]));
    h[2] = __float2bfloat16(x.z); l[2] = __float2bfloat16(x.z - __bfloat162float(h[2]));
    h[3] = __float2bfloat16(x.w); l[3] = __float2bfloat16(x.w - __bfloat162float(h[3]));

    __nv_bfloat16* base = E + (size_t)m * KE + c;
    if (isw) {
        *(uint2*)(base)            = *(uint2*)h;
        *(uint2*)(base + DMODEL)   = *(uint2*)h;
        *(uint2*)(base + 2*DMODEL) = *(uint2*)l;
    } else {
        *(uint2*)(base)            = *(uint2*)h;
        *(uint2*)(base + DMODEL)   = *(uint2*)l;
        *(uint2*)(base + 2*DMODEL) = *(uint2*)h;
    }
}

__global__ __launch_bounds__(256) void expand_acts3(
    const float* __restrict__ X0, const float* __restrict__ X1,
    const float* __restrict__ X2,
    __nv_bfloat16* __restrict__ E0, __nv_bfloat16* __restrict__ E1,
    __nv_bfloat16* __restrict__ E2)
{
    const int t = blockIdx.y;
    const float* X = (t == 0) ? X0 : (t == 1) ? X1 : X2;
    __nv_bfloat16* E = (t == 0) ? E0 : (t == 1) ? E1 : E2;
    expand_row(X, E, false);
}

__global__ __launch_bounds__(256) void expand_w2(
    const float* __restrict__ X0, const float* __restrict__ X1,
    __nv_bfloat16* __restrict__ E0, __nv_bfloat16* __restrict__ E1)
{
    const int t = blockIdx.y;
    expand_row(t ? X1 : X0, t ? E1 : E0, true);
}

__global__ __launch_bounds__(256) void expand3_act(
    const float* __restrict__ X, __nv_bfloat16* __restrict__ E)
{
    expand_row(X, E, false);
}

// ---------------------------------------------------------------------------
// kv_pre (r12 proven): split K and V into bf16 hi/lo tiles, PRE-SWIZZLED.
// tile id = ((b*NH + h)*16 + kt); 128 keys x 64 cols; 128B rows, SW128.
// ---------------------------------------------------------------------------
__global__ __launch_bounds__(256) void kv_pre(
    const float* __restrict__ kp, const float* __restrict__ vp,
    __nv_bfloat16* __restrict__ kx, __nv_bfloat16* __restrict__ vx)
{
    const int tile = blockIdx.x;          // 0..511
    const int kt = tile & 15;
    const int bh = tile >> 4;
    const int b = bh >> 4;
    const int h = bh & 15;
    const int tid = threadIdx.x;

    const size_t src = (size_t)(b * SEQ + kt * 128) * DMODEL + h * DH;
    char* kh = (char*)kx + (size_t)tile * KVTILE_B;
    char* kl = (char*)(kx + KV_LO_ELEMS) + (size_t)tile * KVTILE_B;
    char* vh = (char*)vx + (size_t)tile * KVTILE_B;
    char* vl = (char*)(vx + KV_LO_ELEMS) + (size_t)tile * KVTILE_B;

#pragma unroll
    for (int it = 0; it < 8; it++) {
        int idx = it * 256 + tid;
        int row = idx >> 4;
        int c4 = (idx & 15) * 4;
        uint32_t off = sw128b((uint32_t)row * 128 + c4 * 2);

        float4 xk = *(const float4*)(kp + src + (size_t)row * DMODEL + c4);
        uint32_t h0 = pk2(xk.x, xk.y), h1 = pk2(xk.z, xk.w);
        uint32_t l0 = pk2(xk.x - lof(h0), xk.y - hif(h0));
        uint32_t l1 = pk2(xk.z - lof(h1), xk.w - hif(h1));
        *(uint2*)(kh + off) = make_uint2(h0, h1);
        *(uint2*)(kl + off) = make_uint2(l0, l1);

        float4 xv = *(const float4*)(vp + src + (size_t)row * DMODEL + c4);
        h0 = pk2(xv.x, xv.y); h1 = pk2(xv.z, xv.w);
        l0 = pk2(xv.x - lof(h0), xv.y - hif(h0));
        l1 = pk2(xv.z - lof(h1), xv.w - hif(h1));
        *(uint2*)(vh + off) = make_uint2(h0, h1);
        *(uint2*)(vl + off) = make_uint2(l0, l1);
    }
}

// ---------------------------------------------------------------------------
// Batched bf16 mma.sync GEMM (proven, at legacy-HMMA ceiling)
// ---------------------------------------------------------------------------
#define GBM 256
#define GBN 128
#define GBK 32
#define KITERS (KE / GBK)     // 96
#define STG 3
#define STG_BYTES 24576
#define GSMEM (STG * STG_BYTES)

__global__ __launch_bounds__(256, 1) void gemm3_bf16(
    const __nv_bfloat16* __restrict__ A0, const __nv_bfloat16* __restrict__ A1,
    const __nv_bfloat16* __restrict__ A2,
    const __nv_bfloat16* __restrict__ B0, const __nv_bfloat16* __restrict__ B1,
    const __nv_bfloat16* __restrict__ B2,
    float* __restrict__ C0, float* __restrict__ C1, float* __restrict__ C2)
{
    extern __shared__ __align__(128) char smem[];

    const int z = blockIdx.z;
    const __nv_bfloat16* A = (z == 0) ? A0 : (z == 1) ? A1 : A2;
    const __nv_bfloat16* B = (z == 0) ? B0 : (z == 1) ? B1 : B2;
    float* C = (z == 0) ? C0 : (z == 1) ? C1 : C2;

    const int tid  = threadIdx.x;
    const int lane = tid & 31;
    const int warp = tid >> 5;
    const int wm = (warp >> 1) * 64;
    const int wn = (warp & 1) * 64;
    const int bm0 = blockIdx.y * GBM;
    const int bn0 = blockIdx.x * GBN;

    const int gm = tid >> 2;
    const int gg = tid & 3;
    const __nv_bfloat16* Ag[4];
    const __nv_bfloat16* Bg[2];
    uint32_t soA[4], soB[2];
#pragma unroll
    for (int i = 0; i < 4; i++) {
        Ag[i] = A + (size_t)(bm0 + gm + i * 64) * KE + gg * 8;
        soA[i] = sw64((uint32_t)(gm + i * 64) * 64 + gg * 16);
    }
#pragma unroll
    for (int i = 0; i < 2; i++) {
        Bg[i] = B + (size_t)(bn0 + gm + i * 64) * KE + gg * 8;
        soB[i] = sw64((uint32_t)(gm + i * 64) * 64 + gg * 16);
    }

    const uint32_t sb = (uint32_t)__cvta_generic_to_shared(smem);

    uint32_t a_off[4], b_off[4];
#pragma unroll
    for (int mt = 0; mt < 4; mt++) {
        int r = wm + mt * 16 + (lane & 15);
        a_off[mt] = sw64((uint32_t)r * 64 + (lane >> 4) * 16);
    }
#pragma unroll
    for (int nt2 = 0; nt2 < 4; nt2++) {
        int n = wn + nt2 * 16 + (lane & 7) + ((lane >> 3) & 1) * 8;
        b_off[nt2] = sw64((uint32_t)n * 64 + (lane >> 4) * 16);
    }

    float acc[4][8][4];
#pragma unroll
    for (int i = 0; i < 4; i++)
#pragma unroll
        for (int j = 0; j < 8; j++)
#pragma unroll
            for (int k = 0; k < 4; k++) acc[i][j][k] = 0.0f;

    auto issue_load = [&](int s, int kt) {
        const uint32_t base = sb + s * STG_BYTES;
        const int ko = kt * GBK;
#pragma unroll
        for (int i = 0; i < 4; i++) cpasync16(base + soA[i], Ag[i] + ko);
#pragma unroll
        for (int i = 0; i < 2; i++) cpasync16(base + 16384 + soB[i], Bg[i] + ko);
        cp_commit();
    };

    issue_load(0, 0);
    issue_load(1, 1);

    int s = 0;
    for (int kt = 0; kt < KITERS; kt++) {
        cp_wait1();
        __syncthreads();
        if (kt + 2 < KITERS) {
            int ns = s + 2; if (ns >= STG) ns -= STG;
            issue_load(ns, kt + 2);
        }

        const uint32_t ab = sb + s * STG_BYTES;
        const uint32_t bbb = ab + 16384;
#pragma unroll
        for (int k16 = 0; k16 < 2; k16++) {
            const uint32_t kx = k16 << 5;
            uint32_t ar[4][4];
#pragma unroll
            for (int mt = 0; mt < 4; mt++)
                ldsm4(ar[mt][0], ar[mt][1], ar[mt][2], ar[mt][3],
                      ab + (a_off[mt] ^ kx));
            uint32_t br[4][4];
#pragma unroll
            for (int nt2 = 0; nt2 < 4; nt2++)
                ldsm4(br[nt2][0], br[nt2][1], br[nt2][2], br[nt2][3],
                      bbb + (b_off[nt2] ^ kx));

#pragma unroll
            for (int mt = 0; mt < 4; mt++)
#pragma unroll
                for (int nt = 0; nt < 8; nt++)
                    mma16816(acc[mt][nt], ar[mt],
                             br[nt >> 1][nt & 1], br[nt >> 1][2 + (nt & 1)]);
        }
        __syncthreads();
        if (++s >= STG) s -= STG;
    }

#pragma unroll
    for (int mt = 0; mt < 4; mt++) {
#pragma unroll
        for (int nt = 0; nt < 8; nt++) {
            int row = bm0 + wm + mt * 16 + (lane >> 2);
            int col = bn0 + wn + nt * 8 + (lane & 3) * 2;
            float2 lo = make_float2(acc[mt][nt][0], acc[mt][nt][1]);
            float2 hi = make_float2(acc[mt][nt][2], acc[mt][nt][3]);
            *(float2*)(C + (size_t)row * DMODEL + col) = lo;
            *(float2*)(C + (size_t)(row + 8) * DMODEL + col) = hi;
        }
    }
}

// ---------------------------------------------------------------------------
// Attention (r12 proven): bf16 3-pass QK + bf16 3-term PV, pre-converted KV,
// cp.async double buffer. smem: Q 32KB + 2 x 64KB stages = 160KB.
// ---------------------------------------------------------------------------
#define ATT_SMEM 163840
#define SQH 0
#define SQL 16384
#define ASTG0 32768
#define ASTG_B 65536

__device__ __forceinline__ void cvt_tile_q(char* smem, const float* __restrict__ src)
{
    const int tid = threadIdx.x;
#pragma unroll
    for (int it = 0; it < 8; it++) {
        int idx = it * 256 + tid;
        int row = idx >> 4;
        int c4 = (idx & 15) * 4;
        float4 x = *(const float4*)(src + (size_t)row * DMODEL + c4);
        uint32_t h0 = pk2(x.x, x.y), h1 = pk2(x.z, x.w);
        uint32_t l0 = pk2(x.x - lof(h0), x.y - hif(h0));
        uint32_t l1 = pk2(x.z - lof(h1), x.w - hif(h1));
        uint32_t s = sw128b((uint32_t)row * 128 + c4 * 2);
        *(uint2*)(smem + SQH + s) = make_uint2(h0, h1);
        *(uint2*)(smem + SQL + s) = make_uint2(l0, l1);
    }
}

__global__ __launch_bounds__(256, 1) void attn_tc(
    const float* __restrict__ qp,
    const __nv_bfloat16* __restrict__ kx, const __nv_bfloat16* __restrict__ vx,
    const int* __restrict__ mask, float* __restrict__ outp)
{
    extern __shared__ char smem[];
    const uint32_t sb = (uint32_t)__cvta_generic_to_shared(smem);

    const int tid = threadIdx.x;
    const int lane = tid & 31;
    const int w = tid >> 5;
    const int bh = blockIdx.y;
    const int b = bh >> 4;
    const int h = bh & 15;
    const int q0 = blockIdx.x * 128;

    const int tile0 = bh * 16;
    const char* kh_g = (const char*)kx;
    const char* kl_g = (const char*)(kx + KV_LO_ELEMS);
    const char* vh_g = (const char*)vx;
    const char* vl_g = (const char*)(vx + KV_LO_ELEMS);

    auto load_kv = [&](int st, int kt) {
        const size_t tb = (size_t)(tile0 + kt) * KVTILE_B;
        const uint32_t d = sb + ASTG0 + st * ASTG_B;
#pragma unroll
        for (int i = 0; i < 4; i++) {
            const uint32_t c = (tid + i * 256) * 16;
            cpasync16(d + c,         kh_g + tb + c);
            cpasync16(d + 16384 + c, kl_g + tb + c);
            cpasync16(d + 32768 + c, vh_g + tb + c);
            cpasync16(d + 49152 + c, vl_g + tb + c);
        }
        cp_commit();
    };

    load_kv(0, 0);
    cvt_tile_q(smem, qp + (size_t)(b * SEQ + q0) * DMODEL + h * DH);

    uint32_t offA;
    {
        uint32_t o = (uint32_t)(w * 16 + (lane & 15)) * 128 + (lane >> 4) * 16;
        offA = sw128b(o);
    }
    uint32_t offB[8];
#pragma unroll
    for (int nt2 = 0; nt2 < 8; nt2++) {
        uint32_t r = nt2 * 16 + (lane & 7) + ((lane >> 3) & 1) * 8;
        offB[nt2] = sw128b(r * 128 + (lane >> 4) * 16);
    }
    const int vtl = lane >> 3;
    const int vr8 = lane & 7;
    const int vrow_base = (vtl & 1) * 8 + vr8;
    const int vcol16 = (vtl >> 1) * 16;

    float out[8][4];
#pragma unroll
    for (int i = 0; i < 8; i++)
#pragma unroll
        for (int j = 0; j < 4; j++) out[i][j] = 0.0f;
    float den0 = 0.0f, den1 = 0.0f;

    for (int kt = 0; kt < 16; kt++) {
        if (kt < 15) {
            load_kv((kt + 1) & 1, kt + 1);
            cp_wait1();
        } else {
            cp_wait0();
        }
        __syncthreads();

        const uint32_t stg = sb + ASTG0 + (kt & 1) * ASTG_B;
        const uint32_t KH = stg, KL = stg + 16384;
        const uint32_t VH = stg + 32768, VL = stg + 49152;

        float S[16][4];
#pragma unroll
        for (int i = 0; i < 16; i++)
#pragma unroll
            for (int j = 0; j < 4; j++) S[i][j] = 0.0f;

#pragma unroll
        for (int pass = 0; pass < 3; pass++) {
            const uint32_t abase = sb + (pass == 1 ? SQL : SQH);
            const uint32_t bbase = (pass == 2) ? KL : KH;
#pragma unroll
            for (int ks = 0; ks < 4; ks++) {
                uint32_t a[4];
                ldsm4(a[0], a[1], a[2], a[3], abase + (offA ^ (ks * 32)));
#pragma unroll
                for (int nt2 = 0; nt2 < 8; nt2++) {
                    uint32_t b0, b1, b2, b3;
                    ldsm4(b0, b1, b2, b3, bbase + (offB[nt2] ^ (ks * 32)));
                    mma16816(S[2 * nt2],     a, b0, b2);
                    mma16816(S[2 * nt2 + 1], a, b1, b3);
                }
            }
        }

#pragma unroll
        for (int nt = 0; nt < 16; nt++) {
#pragma unroll
            for (int j = 0; j < 4; j++) {
                float s = fminf(fmaxf(S[nt][j] * 0.125f, -50.0f), 50.0f);
                float p = __expf(s);
                S[nt][j] = p;
                if (j < 2) den0 += p; else den1 += p;
            }
        }

#pragma unroll
        for (int ks = 0; ks < 8; ks++) {
            uint32_t aph[4], apl[4];
            {
                const float* e = S[2 * ks];
                const float* o = S[2 * ks + 1];
                aph[0] = pk2(e[0], e[1]);
                aph[1] = pk2(e[2], e[3]);
                aph[2] = pk2(o[0], o[1]);
                aph[3] = pk2(o[2], o[3]);
                apl[0] = pk2(e[0] - lof(aph[0]), e[1] - hif(aph[0]));
                apl[1] = pk2(e[2] - lof(aph[1]), e[3] - hif(aph[1]));
                apl[2] = pk2(o[0] - lof(aph[2]), o[1] - hif(aph[2]));
                apl[3] = pk2(o[2] - lof(aph[3]), o[3] - hif(aph[3]));
            }
            const uint32_t krow = ks * 16 + vrow_base;
#pragma unroll
            for (int i = 0; i < 4; i++) {
                uint32_t so = sw128b(krow * 128 + i * 32 + vcol16);
                uint32_t b0, b1, b2, b3;
                ldsm4t(b0, b1, b2, b3, VH + so);
                mma16816(out[2 * i],     aph, b0, b1);
                mma16816(out[2 * i + 1], aph, b2, b3);
                mma16816(out[2 * i],     apl, b0, b1);
                mma16816(out[2 * i + 1], apl, b2, b3);
                ldsm4t(b0, b1, b2, b3, VL + so);
                mma16816(out[2 * i],     aph, b0, b1);
                mma16816(out[2 * i + 1], aph, b2, b3);
            }
        }
        __syncthreads();
    }

    den0 += __shfl_xor_sync(0xffffffffu, den0, 1);
    den0 += __shfl_xor_sync(0xffffffffu, den0, 2);
    den1 += __shfl_xor_sync(0xffffffffu, den1, 1);
    den1 += __shfl_xor_sync(0xffffffffu, den1, 2);

    const int grow0 = q0 + w * 16 + (lane >> 2);
    const int grow1 = grow0 + 8;
    const float inv0 = (mask[b * SEQ + grow0] != 0) ? (1.0f / den0) : 0.0f;
    const float inv1 = (mask[b * SEQ + grow1] != 0) ? (1.0f / den1) : 0.0f;

    float* o0 = outp + (size_t)(b * SEQ + grow0) * DMODEL + h * DH + (lane & 3) * 2;
    float* o1 = outp + (size_t)(b * SEQ + grow1) * DMODEL + h * DH + (lane & 3) * 2;
#pragma unroll
    for (int nt = 0; nt < 8; nt++) {
        *(float2*)(o0 + nt * 8) = make_float2(out[nt][0] * inv0, out[nt][1] * inv0);
        *(float2*)(o1 + nt * 8) = make_float2(out[nt][2] * inv1, out[nt][3] * inv1);
    }
}

// ---------------------------------------------------------------------------
extern "C" void kernel_launch(void* const* d_in, const int* in_sizes, int n_in,
                              void* d_out, int out_size)
{
    const float* Q  = (const float*)d_in[0];
    const float* K  = (const float*)d_in[1];
    const float* V  = (const float*)d_in[2];
    const int*   mask = (const int*)d_in[3];
    const float* Wq = (const float*)d_in[4];
    const float* Wk = (const float*)d_in[5];
    const float* Wv = (const float*)d_in[6];
    const float* Wo = (const float*)d_in[7];

    float *qb, *kb, *vb, *ao;
    __nv_bfloat16 *xe, *we;
    cudaGetSymbolAddress((void**)&qb, g_q);
    cudaGetSymbolAddress((void**)&kb, g_k);
    cudaGetSymbolAddress((void**)&vb, g_v);
    cudaGetSymbolAddress((void**)&ao, g_ao);
    cudaGetSymbolAddress((void**)&xe, g_xe);
    cudaGetSymbolAddress((void**)&we, g_we);

    __nv_bfloat16* xe0 = xe;
    __nv_bfloat16* xe1 = xe + (size_t)MROWS * KE;
    __nv_bfloat16* xe2 = xe + 2 * (size_t)MROWS * KE;
    __nv_bfloat16* we0 = we;
    __nv_bfloat16* we1 = we + (size_t)DMODEL * KE;
    __nv_bfloat16* we2 = we + 2 * (size_t)DMODEL * KE;
    __nv_bfloat16* we3 = we + 3 * (size_t)DMODEL * KE;

    cudaFuncSetAttribute(attn_tc, cudaFuncAttributeMaxDynamicSharedMemorySize,
                         ATT_SMEM);
    cudaFuncSetAttribute(gemm3_bf16, cudaFuncAttributeMaxDynamicSharedMemorySize,
                         GSMEM);

    const int EXP_ACT_BLOCKS = MROWS * (DMODEL / 4) / 256;   // 4096
    const int EXP_W_BLOCKS   = DMODEL * (DMODEL / 4) / 256;  // 1024

    // 1-2: weight expansions (split so attn is launch #6 for ncu -s 5)
    dim3 gw(EXP_W_BLOCKS, 2);
    expand_w2<<<gw, 256>>>(Wq, Wk, we0, we1);
    expand_w2<<<gw, 256>>>(Wv, Wo, we2, we3);

    // 3: activation expansions
    dim3 ge1(EXP_ACT_BLOCKS, 3);
    expand_acts3<<<ge1, 256>>>(Q, K, V, xe0, xe1, xe2);

    // 4: batched QKV projection
    dim3 gqkv(DMODEL / GBN, MROWS / GBM, 3);                 // (8, 16, 3)
    gemm3_bf16<<<gqkv, 256, GSMEM>>>(xe0, xe1, xe2, we0, we1, we2, qb, kb, vb);

    // 5: pre-split K/V into swizzled bf16 hi/lo tiles
    kv_pre<<<BB * NH * 16, 256>>>(kb, vb, xe1, xe2);

    // 6: attention  (profiled launch under ncu -s 5 -c 1)
    dim3 ga(SEQ / 128, BB * NH);                             // (16, 32)
    attn_tc<<<ga, 256, ATT_SMEM>>>(qb, xe1, xe2, mask, ao);

    // 7: expand attention output
    expand3_act<<<EXP_ACT_BLOCKS, 256>>>(ao, xe0);

    // 8: O projection
    dim3 go(DMODEL / GBN, MROWS / GBM, 1);
    gemm3_bf16<<<go, 256, GSMEM>>>(xe0, xe0, xe0, we3, we3, we3,
                                   (float*)d_out, (float*)d_out, (float*)d_out);
}

// round 17
// speedup vs baseline: 1.0282x; 1.0282x over previous
#include <cuda_runtime.h>
#include <cuda_bf16.h>
#include <stdint.h>

#define BB 2
#define SEQ 2048
#define DMODEL 1024
#define NH 16
#define DH 64
#define MROWS (BB * SEQ)     // 4096
#define KE (3 * DMODEL)      // 3072

// Scratch (allocation-free)
__device__ float g_q[MROWS * DMODEL];
__device__ float g_k[MROWS * DMODEL];
__device__ float g_v[MROWS * DMODEL];
__device__ float g_ao[MROWS * DMODEL];
__device__ __nv_bfloat16 g_xe[3][(size_t)MROWS * KE];   // 3 x 24 MB
__device__ __nv_bfloat16 g_we[4][(size_t)DMODEL * KE];  // 4 x 6 MB

// packed KV tile geometry: tile = 128 keys x 64 cols bf16 (128B rows, SW128)
#define KVTILE_B 16384
#define KV_LO_ELEMS 4194304   // 512 tiles * 8192 elems (hi buf); lo at +this

// ---------------------------------------------------------------------------
// helpers
// ---------------------------------------------------------------------------
__device__ __forceinline__ uint32_t pk2(float lo, float hi) {
    uint32_t r;
    asm("cvt.rn.bf16x2.f32 %0, %1, %2;" : "=r"(r) : "f"(hi), "f"(lo));
    return r;
}
__device__ __forceinline__ float lof(uint32_t u) { return __uint_as_float(u << 16); }
__device__ __forceinline__ float hif(uint32_t u) { return __uint_as_float(u & 0xffff0000u); }

__device__ __forceinline__ void ldsm4(uint32_t& r0, uint32_t& r1,
                                      uint32_t& r2, uint32_t& r3, uint32_t addr) {
    asm volatile("ldmatrix.sync.aligned.m8n8.x4.shared.b16 {%0,%1,%2,%3}, [%4];"
                 : "=r"(r0), "=r"(r1), "=r"(r2), "=r"(r3) : "r"(addr));
}
__device__ __forceinline__ void ldsm4t(uint32_t& r0, uint32_t& r1,
                                       uint32_t& r2, uint32_t& r3, uint32_t addr) {
    asm volatile("ldmatrix.sync.aligned.m8n8.x4.trans.shared.b16 {%0,%1,%2,%3}, [%4];"
                 : "=r"(r0), "=r"(r1), "=r"(r2), "=r"(r3) : "r"(addr));
}
__device__ __forceinline__ void mma16816(float* d, const uint32_t* a,
                                         uint32_t b0, uint32_t b1) {
    asm volatile(
        "mma.sync.aligned.m16n8k16.row.col.f32.bf16.bf16.f32 "
        "{%0,%1,%2,%3}, {%4,%5,%6,%7}, {%8,%9}, {%0,%1,%2,%3};"
        : "+f"(d[0]), "+f"(d[1]), "+f"(d[2]), "+f"(d[3])
        : "r"(a[0]), "r"(a[1]), "r"(a[2]), "r"(a[3]), "r"(b0), "r"(b1));
}
__device__ __forceinline__ uint32_t sw128b(uint32_t b) {
    return b ^ ((b >> 3) & 0x70);
}
__device__ __forceinline__ uint32_t sw64(uint32_t b) {
    return b ^ ((b >> 3) & 0x30);
}
__device__ __forceinline__ void cpasync16(uint32_t dst, const void* src) {
    asm volatile("cp.async.cg.shared.global [%0], [%1], 16;" :: "r"(dst), "l"(src));
}
__device__ __forceinline__ void cp_commit() {
    asm volatile("cp.async.commit_group;");
}
__device__ __forceinline__ void cp_wait1() {
    asm volatile("cp.async.wait_group 1;");
}
__device__ __forceinline__ void cp_wait0() {
    asm volatile("cp.async.wait_group 0;");
}

// ---------------------------------------------------------------------------
// Expansion: act -> [hi|lo|hi], weights -> [hi|hi|lo]  (proven math)
// ---------------------------------------------------------------------------
__device__ __forceinline__ void expand_row(const float* __restrict__ X,
                                           __nv_bfloat16* __restrict__ E, bool isw)
{
    int idx = blockIdx.x * 256 + threadIdx.x;
    int m = idx >> 8;
    int c = (idx & 255) * 4;
    float4 x = *(const float4*)(X + (size_t)m * DMODEL + c);

    __nv_bfloat16 h[4], l[4];
    h[0] = __float2bfloat16(x.x); l[0] = __float2bfloat16(x.x - __bfloat162float(h[0]));
    h[1] = __float2bfloat16(x.y); l[1] = __float2bfloat16(x.y - __bfloat162float(h[1]));
    h[2] = __float2bfloat16(x.z); l[2] = __float2bfloat16(x.z - __bfloat162float(h[2]));
    h[3] = __float2bfloat16(x.w); l[3] = __float2bfloat16(x.w - __bfloat162float(h[3]));

    __nv_bfloat16* base = E + (size_t)m * KE + c;
    if (isw) {
        *(uint2*)(base)            = *(uint2*)h;
        *(uint2*)(base + DMODEL)   = *(uint2*)h;
        *(uint2*)(base + 2*DMODEL) = *(uint2*)l;
    } else {
        *(uint2*)(base)            = *(uint2*)h;
        *(uint2*)(base + DMODEL)   = *(uint2*)l;
        *(uint2*)(base + 2*DMODEL) = *(uint2*)h;
    }
}

__global__ __launch_bounds__(256) void expand_acts3(
    const float* __restrict__ X0, const float* __restrict__ X1,
    const float* __restrict__ X2,
    __nv_bfloat16* __restrict__ E0, __nv_bfloat16* __restrict__ E1,
    __nv_bfloat16* __restrict__ E2)
{
    const int t = blockIdx.y;
    const float* X = (t == 0) ? X0 : (t == 1) ? X1 : X2;
    __nv_bfloat16* E = (t == 0) ? E0 : (t == 1) ? E1 : E2;
    expand_row(X, E, false);
}

__global__ __launch_bounds__(256) void expand_w2(
    const float* __restrict__ X0, const float* __restrict__ X1,
    __nv_bfloat16* __restrict__ E0, __nv_bfloat16* __restrict__ E1)
{
    const int t = blockIdx.y;
    expand_row(t ? X1 : X0, t ? E1 : E0, true);
}

__global__ __launch_bounds__(256) void expand3_act(
    const float* __restrict__ X, __nv_bfloat16* __restrict__ E)
{
    expand_row(X, E, false);
}

// ---------------------------------------------------------------------------
// kv_pre (proven): split K and V into bf16 hi/lo tiles, PRE-SWIZZLED.
// ---------------------------------------------------------------------------
__global__ __launch_bounds__(256) void kv_pre(
    const float* __restrict__ kp, const float* __restrict__ vp,
    __nv_bfloat16* __restrict__ kx, __nv_bfloat16* __restrict__ vx)
{
    const int tile = blockIdx.x;          // 0..511
    const int kt = tile & 15;
    const int bh = tile >> 4;
    const int b = bh >> 4;
    const int h = bh & 15;
    const int tid = threadIdx.x;

    const size_t src = (size_t)(b * SEQ + kt * 128) * DMODEL + h * DH;
    char* kh = (char*)kx + (size_t)tile * KVTILE_B;
    char* kl = (char*)(kx + KV_LO_ELEMS) + (size_t)tile * KVTILE_B;
    char* vh = (char*)vx + (size_t)tile * KVTILE_B;
    char* vl = (char*)(vx + KV_LO_ELEMS) + (size_t)tile * KVTILE_B;

#pragma unroll
    for (int it = 0; it < 8; it++) {
        int idx = it * 256 + tid;
        int row = idx >> 4;
        int c4 = (idx & 15) * 4;
        uint32_t off = sw128b((uint32_t)row * 128 + c4 * 2);

        float4 xk = *(const float4*)(kp + src + (size_t)row * DMODEL + c4);
        uint32_t h0 = pk2(xk.x, xk.y), h1 = pk2(xk.z, xk.w);
        uint32_t l0 = pk2(xk.x - lof(h0), xk.y - hif(h0));
        uint32_t l1 = pk2(xk.z - lof(h1), xk.w - hif(h1));
        *(uint2*)(kh + off) = make_uint2(h0, h1);
        *(uint2*)(kl + off) = make_uint2(l0, l1);

        float4 xv = *(const float4*)(vp + src + (size_t)row * DMODEL + c4);
        h0 = pk2(xv.x, xv.y); h1 = pk2(xv.z, xv.w);
        l0 = pk2(xv.x - lof(h0), xv.y - hif(h0));
        l1 = pk2(xv.z - lof(h1), xv.w - hif(h1));
        *(uint2*)(vh + off) = make_uint2(h0, h1);
        *(uint2*)(vl + off) = make_uint2(l0, l1);
    }
}

// ---------------------------------------------------------------------------
// Batched bf16 mma.sync GEMM — now 512 threads = 16 warps (4m x 4n),
// warp tile 64x32 -> acc 64 regs/thread, 4 warps/SMSP for latency hiding.
// CTA tile 256x128, BK=32, 3-stage cp.async. grid.z selects (A,B,C).
// ---------------------------------------------------------------------------
#define GBM 256
#define GBN 128
#define GBK 32
#define KITERS (KE / GBK)     // 96
#define STG 3
#define STG_BYTES 24576       // A 16KB + B 8KB
#define GSMEM (STG * STG_BYTES)

__global__ __launch_bounds__(512, 1) void gemm3_bf16(
    const __nv_bfloat16* __restrict__ A0, const __nv_bfloat16* __restrict__ A1,
    const __nv_bfloat16* __restrict__ A2,
    const __nv_bfloat16* __restrict__ B0, const __nv_bfloat16* __restrict__ B1,
    const __nv_bfloat16* __restrict__ B2,
    float* __restrict__ C0, float* __restrict__ C1, float* __restrict__ C2)
{
    extern __shared__ __align__(128) char smem[];

    const int z = blockIdx.z;
    const __nv_bfloat16* A = (z == 0) ? A0 : (z == 1) ? A1 : A2;
    const __nv_bfloat16* B = (z == 0) ? B0 : (z == 1) ? B1 : B2;
    float* C = (z == 0) ? C0 : (z == 1) ? C1 : C2;

    const int tid  = threadIdx.x;
    const int lane = tid & 31;
    const int warp = tid >> 5;          // 0..15
    const int wm = (warp >> 2) * 64;    // 0,64,128,192
    const int wn = (warp & 3) * 32;     // 0,32,64,96
    const int bm0 = blockIdx.y * GBM;
    const int bn0 = blockIdx.x * GBN;

    // g2s: 512 threads, A needs 1024 16B-chunks (2/thread), B 512 (1/thread)
    const int gm = tid >> 2;            // 0..127
    const int gg = tid & 3;
    const __nv_bfloat16* Ag[2];
    const __nv_bfloat16* Bg1;
    uint32_t soA[2], soB1;
#pragma unroll
    for (int i = 0; i < 2; i++) {
        Ag[i] = A + (size_t)(bm0 + gm + i * 128) * KE + gg * 8;
        soA[i] = sw64((uint32_t)(gm + i * 128) * 64 + gg * 16);
    }
    Bg1 = B + (size_t)(bn0 + gm) * KE + gg * 8;
    soB1 = sw64((uint32_t)gm * 64 + gg * 16);

    const uint32_t sb = (uint32_t)__cvta_generic_to_shared(smem);

    uint32_t a_off[4], b_off[2];
#pragma unroll
    for (int mt = 0; mt < 4; mt++) {
        int r = wm + mt * 16 + (lane & 15);
        a_off[mt] = sw64((uint32_t)r * 64 + (lane >> 4) * 16);
    }
#pragma unroll
    for (int nt2 = 0; nt2 < 2; nt2++) {
        int n = wn + nt2 * 16 + (lane & 7) + ((lane >> 3) & 1) * 8;
        b_off[nt2] = sw64((uint32_t)n * 64 + (lane >> 4) * 16);
    }

    float acc[4][4][4];
#pragma unroll
    for (int i = 0; i < 4; i++)
#pragma unroll
        for (int j = 0; j < 4; j++)
#pragma unroll
            for (int k = 0; k < 4; k++) acc[i][j][k] = 0.0f;

    auto issue_load = [&](int s, int kt) {
        const uint32_t base = sb + s * STG_BYTES;
        const int ko = kt * GBK;
        cpasync16(base + soA[0], Ag[0] + ko);
        cpasync16(base + soA[1], Ag[1] + ko);
        cpasync16(base + 16384 + soB1, Bg1 + ko);
        cp_commit();
    };

    issue_load(0, 0);
    issue_load(1, 1);

    int s = 0;
    for (int kt = 0; kt < KITERS; kt++) {
        cp_wait1();
        __syncthreads();
        if (kt + 2 < KITERS) {
            int ns = s + 2; if (ns >= STG) ns -= STG;
            issue_load(ns, kt + 2);
        }

        const uint32_t ab = sb + s * STG_BYTES;
        const uint32_t bbb = ab + 16384;
#pragma unroll
        for (int k16 = 0; k16 < 2; k16++) {
            const uint32_t kx = k16 << 5;
            uint32_t ar[4][4];
#pragma unroll
            for (int mt = 0; mt < 4; mt++)
                ldsm4(ar[mt][0], ar[mt][1], ar[mt][2], ar[mt][3],
                      ab + (a_off[mt] ^ kx));
            uint32_t br[2][4];
#pragma unroll
            for (int nt2 = 0; nt2 < 2; nt2++)
                ldsm4(br[nt2][0], br[nt2][1], br[nt2][2], br[nt2][3],
                      bbb + (b_off[nt2] ^ kx));

#pragma unroll
            for (int mt = 0; mt < 4; mt++)
#pragma unroll
                for (int nt = 0; nt < 4; nt++)
                    mma16816(acc[mt][nt], ar[mt],
                             br[nt >> 1][nt & 1], br[nt >> 1][2 + (nt & 1)]);
        }
        __syncthreads();
        if (++s >= STG) s -= STG;
    }

#pragma unroll
    for (int mt = 0; mt < 4; mt++) {
#pragma unroll
        for (int nt = 0; nt < 4; nt++) {
            int row = bm0 + wm + mt * 16 + (lane >> 2);
            int col = bn0 + wn + nt * 8 + (lane & 3) * 2;
            float2 lo = make_float2(acc[mt][nt][0], acc[mt][nt][1]);
            float2 hi = make_float2(acc[mt][nt][2], acc[mt][nt][3]);
            *(float2*)(C + (size_t)row * DMODEL + col) = lo;
            *(float2*)(C + (size_t)(row + 8) * DMODEL + col) = hi;
        }
    }
}

// ---------------------------------------------------------------------------
// Attention (r12/r15 proven): bf16 3-pass QK + bf16 3-term PV, pre-converted
// KV, cp.async double buffer. smem: Q 32KB + 2 x 64KB stages = 160KB.
// ---------------------------------------------------------------------------
#define ATT_SMEM 163840
#define SQH 0
#define SQL 16384
#define ASTG0 32768
#define ASTG_B 65536

__device__ __forceinline__ void cvt_tile_q(char* smem, const float* __restrict__ src)
{
    const int tid = threadIdx.x;
#pragma unroll
    for (int it = 0; it < 8; it++) {
        int idx = it * 256 + tid;
        int row = idx >> 4;
        int c4 = (idx & 15) * 4;
        float4 x = *(const float4*)(src + (size_t)row * DMODEL + c4);
        uint32_t h0 = pk2(x.x, x.y), h1 = pk2(x.z, x.w);
        uint32_t l0 = pk2(x.x - lof(h0), x.y - hif(h0));
        uint32_t l1 = pk2(x.z - lof(h1), x.w - hif(h1));
        uint32_t s = sw128b((uint32_t)row * 128 + c4 * 2);
        *(uint2*)(smem + SQH + s) = make_uint2(h0, h1);
        *(uint2*)(smem + SQL + s) = make_uint2(l0, l1);
    }
}

__global__ __launch_bounds__(256, 1) void attn_tc(
    const float* __restrict__ qp,
    const __nv_bfloat16* __restrict__ kx, const __nv_bfloat16* __restrict__ vx,
    const int* __restrict__ mask, float* __restrict__ outp)
{
    extern __shared__ char smem[];
    const uint32_t sb = (uint32_t)__cvta_generic_to_shared(smem);

    const int tid = threadIdx.x;
    const int lane = tid & 31;
    const int w = tid >> 5;
    const int bh = blockIdx.y;
    const int b = bh >> 4;
    const int h = bh & 15;
    const int q0 = blockIdx.x * 128;

    const int tile0 = bh * 16;
    const char* kh_g = (const char*)kx;
    const char* kl_g = (const char*)(kx + KV_LO_ELEMS);
    const char* vh_g = (const char*)vx;
    const char* vl_g = (const char*)(vx + KV_LO_ELEMS);

    auto load_kv = [&](int st, int kt) {
        const size_t tb = (size_t)(tile0 + kt) * KVTILE_B;
        const uint32_t d = sb + ASTG0 + st * ASTG_B;
#pragma unroll
        for (int i = 0; i < 4; i++) {
            const uint32_t c = (tid + i * 256) * 16;
            cpasync16(d + c,         kh_g + tb + c);
            cpasync16(d + 16384 + c, kl_g + tb + c);
            cpasync16(d + 32768 + c, vh_g + tb + c);
            cpasync16(d + 49152 + c, vl_g + tb + c);
        }
        cp_commit();
    };

    load_kv(0, 0);
    cvt_tile_q(smem, qp + (size_t)(b * SEQ + q0) * DMODEL + h * DH);

    uint32_t offA;
    {
        uint32_t o = (uint32_t)(w * 16 + (lane & 15)) * 128 + (lane >> 4) * 16;
        offA = sw128b(o);
    }
    uint32_t offB[8];
#pragma unroll
    for (int nt2 = 0; nt2 < 8; nt2++) {
        uint32_t r = nt2 * 16 + (lane & 7) + ((lane >> 3) & 1) * 8;
        offB[nt2] = sw128b(r * 128 + (lane >> 4) * 16);
    }
    const int vtl = lane >> 3;
    const int vr8 = lane & 7;
    const int vrow_base = (vtl & 1) * 8 + vr8;
    const int vcol16 = (vtl >> 1) * 16;

    float out[8][4];
#pragma unroll
    for (int i = 0; i < 8; i++)
#pragma unroll
        for (int j = 0; j < 4; j++) out[i][j] = 0.0f;
    float den0 = 0.0f, den1 = 0.0f;

    for (int kt = 0; kt < 16; kt++) {
        if (kt < 15) {
            load_kv((kt + 1) & 1, kt + 1);
            cp_wait1();
        } else {
            cp_wait0();
        }
        __syncthreads();

        const uint32_t stg = sb + ASTG0 + (kt & 1) * ASTG_B;
        const uint32_t KH = stg, KL = stg + 16384;
        const uint32_t VH = stg + 32768, VL = stg + 49152;

        float S[16][4];
#pragma unroll
        for (int i = 0; i < 16; i++)
#pragma unroll
            for (int j = 0; j < 4; j++) S[i][j] = 0.0f;

#pragma unroll
        for (int pass = 0; pass < 3; pass++) {
            const uint32_t abase = sb + (pass == 1 ? SQL : SQH);
            const uint32_t bbase = (pass == 2) ? KL : KH;
#pragma unroll
            for (int ks = 0; ks < 4; ks++) {
                uint32_t a[4];
                ldsm4(a[0], a[1], a[2], a[3], abase + (offA ^ (ks * 32)));
#pragma unroll
                for (int nt2 = 0; nt2 < 8; nt2++) {
                    uint32_t b0, b1, b2, b3;
                    ldsm4(b0, b1, b2, b3, bbase + (offB[nt2] ^ (ks * 32)));
                    mma16816(S[2 * nt2],     a, b0, b2);
                    mma16816(S[2 * nt2 + 1], a, b1, b3);
                }
            }
        }

#pragma unroll
        for (int nt = 0; nt < 16; nt++) {
#pragma unroll
            for (int j = 0; j < 4; j++) {
                float s = fminf(fmaxf(S[nt][j] * 0.125f, -50.0f), 50.0f);
                float p = __expf(s);
                S[nt][j] = p;
                if (j < 2) den0 += p; else den1 += p;
            }
        }

#pragma unroll
        for (int ks = 0; ks < 8; ks++) {
            uint32_t aph[4], apl[4];
            {
                const float* e = S[2 * ks];
                const float* o = S[2 * ks + 1];
                aph[0] = pk2(e[0], e[1]);
                aph[1] = pk2(e[2], e[3]);
                aph[2] = pk2(o[0], o[1]);
                aph[3] = pk2(o[2], o[3]);
                apl[0] = pk2(e[0] - lof(aph[0]), e[1] - hif(aph[0]));
                apl[1] = pk2(e[2] - lof(aph[1]), e[3] - hif(aph[1]));
                apl[2] = pk2(o[0] - lof(aph[2]), o[1] - hif(aph[2]));
                apl[3] = pk2(o[2] - lof(aph[3]), o[3] - hif(aph[3]));
            }
            const uint32_t krow = ks * 16 + vrow_base;
#pragma unroll
            for (int i = 0; i < 4; i++) {
                uint32_t so = sw128b(krow * 128 + i * 32 + vcol16);
                uint32_t b0, b1, b2, b3;
                ldsm4t(b0, b1, b2, b3, VH + so);
                mma16816(out[2 * i],     aph, b0, b1);
                mma16816(out[2 * i + 1], aph, b2, b3);
                mma16816(out[2 * i],     apl, b0, b1);
                mma16816(out[2 * i + 1], apl, b2, b3);
                ldsm4t(b0, b1, b2, b3, VL + so);
                mma16816(out[2 * i],     aph, b0, b1);
                mma16816(out[2 * i + 1], aph, b2, b3);
            }
        }
        __syncthreads();
    }

    den0 += __shfl_xor_sync(0xffffffffu, den0, 1);
    den0 += __shfl_xor_sync(0xffffffffu, den0, 2);
    den1 += __shfl_xor_sync(0xffffffffu, den1, 1);
    den1 += __shfl_xor_sync(0xffffffffu, den1, 2);

    const int grow0 = q0 + w * 16 + (lane >> 2);
    const int grow1 = grow0 + 8;
    const float inv0 = (mask[b * SEQ + grow0] != 0) ? (1.0f / den0) : 0.0f;
    const float inv1 = (mask[b * SEQ + grow1] != 0) ? (1.0f / den1) : 0.0f;

    float* o0 = outp + (size_t)(b * SEQ + grow0) * DMODEL + h * DH + (lane & 3) * 2;
    float* o1 = outp + (size_t)(b * SEQ + grow1) * DMODEL + h * DH + (lane & 3) * 2;
#pragma unroll
    for (int nt = 0; nt < 8; nt++) {
        *(float2*)(o0 + nt * 8) = make_float2(out[nt][0] * inv0, out[nt][1] * inv0);
        *(float2*)(o1 + nt * 8) = make_float2(out[nt][2] * inv1, out[nt][3] * inv1);
    }
}

// ---------------------------------------------------------------------------
extern "C" void kernel_launch(void* const* d_in, const int* in_sizes, int n_in,
                              void* d_out, int out_size)
{
    const float* Q  = (const float*)d_in[0];
    const float* K  = (const float*)d_in[1];
    const float* V  = (const float*)d_in[2];
    const int*   mask = (const int*)d_in[3];
    const float* Wq = (const float*)d_in[4];
    const float* Wk = (const float*)d_in[5];
    const float* Wv = (const float*)d_in[6];
    const float* Wo = (const float*)d_in[7];

    float *qb, *kb, *vb, *ao;
    __nv_bfloat16 *xe, *we;
    cudaGetSymbolAddress((void**)&qb, g_q);
    cudaGetSymbolAddress((void**)&kb, g_k);
    cudaGetSymbolAddress((void**)&vb, g_v);
    cudaGetSymbolAddress((void**)&ao, g_ao);
    cudaGetSymbolAddress((void**)&xe, g_xe);
    cudaGetSymbolAddress((void**)&we, g_we);

    __nv_bfloat16* xe0 = xe;
    __nv_bfloat16* xe1 = xe + (size_t)MROWS * KE;
    __nv_bfloat16* xe2 = xe + 2 * (size_t)MROWS * KE;
    __nv_bfloat16* we0 = we;
    __nv_bfloat16* we1 = we + (size_t)DMODEL * KE;
    __nv_bfloat16* we2 = we + 2 * (size_t)DMODEL * KE;
    __nv_bfloat16* we3 = we + 3 * (size_t)DMODEL * KE;

    cudaFuncSetAttribute(attn_tc, cudaFuncAttributeMaxDynamicSharedMemorySize,
                         ATT_SMEM);
    cudaFuncSetAttribute(gemm3_bf16, cudaFuncAttributeMaxDynamicSharedMemorySize,
                         GSMEM);

    const int EXP_ACT_BLOCKS = MROWS * (DMODEL / 4) / 256;   // 4096
    const int EXP_W_BLOCKS   = DMODEL * (DMODEL / 4) / 256;  // 1024

    // 1-2: weight expansions
    dim3 gw(EXP_W_BLOCKS, 2);
    expand_w2<<<gw, 256>>>(Wq, Wk, we0, we1);
    expand_w2<<<gw, 256>>>(Wv, Wo, we2, we3);

    // 3: activation expansions
    dim3 ge1(EXP_ACT_BLOCKS, 3);
    expand_acts3<<<ge1, 256>>>(Q, K, V, xe0, xe1, xe2);

    // 4: batched QKV projection (512 threads now)
    dim3 gqkv(DMODEL / GBN, MROWS / GBM, 3);                 // (8, 16, 3)
    gemm3_bf16<<<gqkv, 512, GSMEM>>>(xe0, xe1, xe2, we0, we1, we2, qb, kb, vb);

    // 5: pre-split K/V into swizzled bf16 hi/lo tiles
    kv_pre<<<BB * NH * 16, 256>>>(kb, vb, xe1, xe2);

    // 6: attention  (profiled launch under ncu -s 5 -c 1)
    dim3 ga(SEQ / 128, BB * NH);                             // (16, 32)
    attn_tc<<<ga, 256, ATT_SMEM>>>(qb, xe1, xe2, mask, ao);

    // 7: expand attention output
    expand3_act<<<EXP_ACT_BLOCKS, 256>>>(ao, xe0);

    // 8: O projection
    dim3 go(DMODEL / GBN, MROWS / GBM, 1);
    gemm3_bf16<<<go, 512, GSMEM>>>(xe0, xe0, xe0, we3, we3, we3,
                                   (float*)d_out, (float*)d_out, (float*)d_out);
}